// round 17
// baseline (speedup 1.0000x reference)
#include <cuda_runtime.h>
#include <cuda_fp16.h>
#include <cstdint>

#define BATCH  131072
#define TSTEPS 6
#define NV     31
#define NL     3
#define NT     128
#define ROWS_PER_WARP 16
#define ROWS_PER_CTA  64   // 4 warps * 16

__device__ __forceinline__ void mma_f16(float* D, uint32_t a0, uint32_t a1,
                                        uint32_t a2, uint32_t a3,
                                        uint32_t b0, uint32_t b1){
    asm volatile("mma.sync.aligned.m16n8k16.row.col.f32.f16.f16.f32 "
                 "{%0,%1,%2,%3}, {%4,%5,%6,%7}, {%8,%9}, {%0,%1,%2,%3};"
                 : "+f"(D[0]), "+f"(D[1]), "+f"(D[2]), "+f"(D[3])
                 : "r"(a0), "r"(a1), "r"(a2), "r"(a3), "r"(b0), "r"(b1));
}
// MUFU.TANH: 1 instr, max rel err ~2^-11 (~5e-4) -- calibrated acceptable vs 1e-3 gate
__device__ __forceinline__ float fast_tanh(float x){
    float y;
    asm("tanh.approx.f32 %0, %1;" : "=f"(y) : "f"(x));
    return y;
}
__device__ __forceinline__ uint32_t h2u(__half2 h){ return *(uint32_t*)&h; }
__device__ __forceinline__ uint32_t pack2(float x, float y){
    return h2u(__floats2half2_rn(x, y));
}

// D[4][4] += A(frags, M=16, f16 hi only) x W^T (exact W = Whi + Wlo), 2-product
__device__ __forceinline__ void accum_frag(float D[4][4],
                                           const uint32_t (&A)[2][4],
                                           const uint32_t* __restrict__ wm, int lane){
    #pragma unroll
    for (int kt = 0; kt < 2; kt++){
        uint4 wv[4];
        #pragma unroll
        for (int nt = 0; nt < 4; nt++)
            wv[nt] = ((const uint4*)wm)[(kt*4 + nt)*32 + lane];
        #pragma unroll
        for (int nt = 0; nt < 4; nt++){
            mma_f16(D[nt], A[kt][0], A[kt][1], A[kt][2], A[kt][3], wv[nt].x, wv[nt].y);
            mma_f16(D[nt], A[kt][0], A[kt][1], A[kt][2], A[kt][3], wv[nt].z, wv[nt].w);
        }
    }
}

__global__ void __launch_bounds__(NT, 6)
rnn_tanha(const float* __restrict__ inp,  const float* __restrict__ h0,
          const float* __restrict__ W_ih, const float* __restrict__ W_hh,
          const float* __restrict__ b_ih, const float* __restrict__ b_hh,
          const float* __restrict__ W_lin,const float* __restrict__ b_lin,
          float* __restrict__ out)
{
    __shared__ __align__(16) uint32_t sW[7*1024];   // 7 matrices, B-frag order, f16 hi/lo
    __shared__ float sBias[128];

    const int tid  = threadIdx.x;
    const int lane = tid & 31;
    const int g = lane >> 2, t = lane & 3;
    const size_t b0w = (size_t)blockIdx.x * ROWS_PER_CTA + (size_t)(tid >> 5) * ROWS_PER_WARP;

    // ---- one-time weight pack (verified layout from rounds 5-13) ----
    // idx = (((m*2+kt)*4+nt)*32+lane)*4 + s ; s: 0=b0hi 1=b1hi 2=b0lo 3=b1lo
    for (int idx = tid; idx < 7*1024; idx += NT){
        int s  = idx & 3;
        int ln = (idx >> 2) & 31;
        int nt = (idx >> 7) & 3;
        int kt = (idx >> 9) & 1;
        int m  = idx >> 10;
        int j = nt*8 + (ln >> 2);
        int k = kt*16 + 2*(ln & 3) + (s & 1)*8;
        const float* srcm = (m < 3) ? (W_ih + m*NV*NV)
                          : (m < 6) ? (W_hh + (m-3)*NV*NV)
                                    : W_lin;
        float v0 = (j < NV && k   < NV) ? srcm[j*NV + k]   : 0.0f;
        float v1 = (j < NV && k+1 < NV) ? srcm[j*NV + k+1] : 0.0f;
        __half2 hi = __floats2half2_rn(v0, v1);
        if (s >> 1){
            float2 hf = __half22float2(hi);
            sW[idx] = h2u(__floats2half2_rn(v0 - hf.x, v1 - hf.y));
        } else {
            sW[idx] = h2u(hi);
        }
    }
    {
        int l = tid >> 5, j = tid & 31;
        float v = 0.0f;
        if (j < NV) v = (l < 3) ? (b_ih[l*NV + j] + b_hh[l*NV + j]) : b_lin[j];
        sBias[l*32 + j] = v;
    }
    __syncthreads();
    // ---- warps fully independent; no syncs, no smem state from here ----

    uint32_t ha[NL][2][4];   // per-layer h as A-fragments (f16 hi), M=16

    // h0 -> fragments (direct gmem, scalar loads, col-31 guarded)
    #pragma unroll
    for (int l = 0; l < NL; l++){
        const float* src = h0 + ((size_t)l * BATCH + b0w) * NV;
        const float* r0p = src + g * NV;
        const float* r1p = r0p + 8 * NV;
        #pragma unroll
        for (int kt = 0; kt < 2; kt++){
            int c0 = kt*16 + 2*t, c1 = c0 + 8;
            float e1 = 0.f, f1 = 0.f;
            if (!(kt == 1 && t == 3)){ e1 = r0p[c1+1]; f1 = r1p[c1+1]; }
            ha[l][kt][0] = pack2(r0p[c0], r0p[c0+1]);
            ha[l][kt][1] = pack2(r1p[c0], r1p[c0+1]);
            ha[l][kt][2] = pack2(r0p[c1], e1);
            ha[l][kt][3] = pack2(r1p[c1], f1);
        }
    }

    float D[4][4];

    #pragma unroll 1
    for (int ts = 0; ts < TSTEPS; ts++){
        #pragma unroll
        for (int l = 0; l < NL; l++){
            // init D from combined bias
            #pragma unroll
            for (int nt = 0; nt < 4; nt++){
                float bA = sBias[l*32 + nt*8 + 2*t];
                float bB = sBias[l*32 + nt*8 + 2*t + 1];
                D[nt][0] = bA; D[nt][1] = bB; D[nt][2] = bA; D[nt][3] = bB;
            }
            // input accumulation
            if (l == 0){
                const float* rp = inp + (b0w + g) * (TSTEPS*NV) + ts*NV;
                const float* rq = rp + 8 * (TSTEPS*NV);
                uint32_t xa[2][4];
                #pragma unroll
                for (int kt = 0; kt < 2; kt++){
                    int c0 = kt*16 + 2*t, c1 = c0 + 8;
                    float e1 = 0.f, f1 = 0.f;
                    if (!(kt == 1 && t == 3)){ e1 = rp[c1+1]; f1 = rq[c1+1]; }
                    xa[kt][0] = pack2(rp[c0], rp[c0+1]);
                    xa[kt][1] = pack2(rq[c0], rq[c0+1]);
                    xa[kt][2] = pack2(rp[c1], e1);
                    xa[kt][3] = pack2(rq[c1], f1);
                }
                accum_frag(D, xa, sW, lane);
            } else {
                accum_frag(D, ha[l-1], sW + l*1024, lane);
            }
            // recurrent accumulation
            accum_frag(D, ha[l], sW + (3+l)*1024, lane);

            // epilogue: tanh -> next A-fragments, all in registers
            #pragma unroll
            for (int kt = 0; kt < 2; kt++){
                ha[l][kt][0] = pack2(fast_tanh(D[2*kt][0]),   fast_tanh(D[2*kt][1]));
                ha[l][kt][1] = pack2(fast_tanh(D[2*kt][2]),   fast_tanh(D[2*kt][3]));
                ha[l][kt][2] = pack2(fast_tanh(D[2*kt+1][0]), fast_tanh(D[2*kt+1][1]));
                ha[l][kt][3] = pack2(fast_tanh(D[2*kt+1][2]), fast_tanh(D[2*kt+1][3]));
            }
        }
    }

    // ---- final linear + tanh ----
    #pragma unroll
    for (int nt = 0; nt < 4; nt++){
        float bA = sBias[3*32 + nt*8 + 2*t];
        float bB = sBias[3*32 + nt*8 + 2*t + 1];
        D[nt][0] = bA; D[nt][1] = bB; D[nt][2] = bA; D[nt][3] = bB;
    }
    accum_frag(D, ha[2], sW + 6*1024, lane);
    #pragma unroll
    for (int nt = 0; nt < 4; nt++)
        #pragma unroll
        for (int i = 0; i < 4; i++)
            D[nt][i] = fast_tanh(D[nt][i]);
    if (t == 3){ D[3][1] = -3.0e38f; D[3][3] = -3.0e38f; }

    // ---- softmax per row (across quad lanes) + direct store ----
    #pragma unroll
    for (int hh = 0; hh < 2; hh++){
        float m = -3.0e38f;
        #pragma unroll
        for (int nt = 0; nt < 4; nt++)
            m = fmaxf(m, fmaxf(D[nt][2*hh], D[nt][2*hh+1]));
        m = fmaxf(m, __shfl_xor_sync(0xffffffffu, m, 1));
        m = fmaxf(m, __shfl_xor_sync(0xffffffffu, m, 2));
        float s = 0.0f;
        #pragma unroll
        for (int nt = 0; nt < 4; nt++){
            float e0 = __expf(D[nt][2*hh]   - m);
            float e1 = __expf(D[nt][2*hh+1] - m);
            D[nt][2*hh] = e0; D[nt][2*hh+1] = e1;
            s += e0 + e1;
        }
        s += __shfl_xor_sync(0xffffffffu, s, 1);
        s += __shfl_xor_sync(0xffffffffu, s, 2);
        float inv = __fdividef(1.0f, s);
        size_t ro = (b0w + g + 8*hh) * (size_t)NV;
        #pragma unroll
        for (int nt = 0; nt < 4; nt++){
            int c = nt*8 + 2*t;
            out[ro + c] = D[nt][2*hh] * inv;
            if (c + 1 < NV) out[ro + c + 1] = D[nt][2*hh+1] * inv;
        }
    }
}

extern "C" void kernel_launch(void* const* d_in, const int* in_sizes, int n_in,
                              void* d_out, int out_size)
{
    const float* inp   = (const float*)d_in[0];
    const float* h0    = (const float*)d_in[1];
    const float* W_ih  = (const float*)d_in[2];
    const float* W_hh  = (const float*)d_in[3];
    const float* b_ih  = (const float*)d_in[4];
    const float* b_hh  = (const float*)d_in[5];
    const float* W_lin = (const float*)d_in[6];
    const float* b_lin = (const float*)d_in[7];
    float* out = (float*)d_out;

    rnn_tanha<<<BATCH / ROWS_PER_CTA, NT>>>(inp, h0, W_ih, W_hh, b_ih, b_hh,
                                            W_lin, b_lin, out);
}